// round 14
// baseline (speedup 1.0000x reference)
#include <cuda_runtime.h>
#include <cuda_fp16.h>
#include <mma.h>
#include <math.h>

using namespace nvcuda;
typedef __half f16;

#define BSZ 16
#define CCH 512
#define NSP 1024
#define NGROUPS 32

#define BM 128
#define BN 128
#define BK 32
#define PAD 8
#define NTHR 128
#define WSCALE 4096.0f

// Scratch (device globals -- no allocation allowed).
__device__ __align__(16) f16 g_h[(long)BSZ*CCH*NSP];
__device__ __align__(16) f16 g_qk[(long)BSZ*NSP*NSP];    // per batch: q rows 0..511 (pre-scaled), k rows 512..1023
__device__ __align__(16) f16 g_attn[(long)BSZ*NSP*NSP];
__device__ __align__(16) f16 g_vo[(long)BSZ*CCH*NSP];    // vo = wvo @ h
__device__ __align__(16) f16 g_w16[4L*CCH*CCH];          // wq | wk | wv | wo*WSCALE
__device__ __align__(16) f16 g_wvo[(long)CCH*CCH];       // (wo*WSCALE) @ wv
__device__ float g_bqk[2*CCH];
__device__ float g_bvo[CCH];

template<bool C, class T, class F> struct Sel { using type = T; };
template<class T, class F> struct Sel<false, T, F> { using type = F; };

__device__ __forceinline__ unsigned pkh(float a, float b) {
    __half2 t = __floats2half2_rn(a, b);
    return *(unsigned*)&t;
}

__device__ __forceinline__ void cp16(void* s, const void* g) {
    unsigned sa = (unsigned)__cvta_generic_to_shared(s);
    asm volatile("cp.async.cg.shared.global [%0], [%1], 16;" :: "r"(sa), "l"(g));
}
__device__ __forceinline__ void cp_commit() { asm volatile("cp.async.commit_group;"); }
__device__ __forceinline__ void cp_wait1() { asm volatile("cp.async.wait_group 1;"); }
__device__ __forceinline__ void cp_wait0() { asm volatile("cp.async.wait_group 0;"); }

__device__ __forceinline__ float blockReduceSum(float v, float* sh) {
    int lane = threadIdx.x & 31, w = threadIdx.x >> 5;
    #pragma unroll
    for (int o = 16; o; o >>= 1) v += __shfl_down_sync(0xffffffffu, v, o);
    if (lane == 0) sh[w] = v;
    __syncthreads();
    if (w == 0) {
        float r = (lane < (int)(blockDim.x >> 5)) ? sh[lane] : 0.f;
        #pragma unroll
        for (int o = 16; o; o >>= 1) r += __shfl_down_sync(0xffffffffu, r, o);
        if (lane == 0) sh[0] = r;
    }
    __syncthreads();
    float r = sh[0];
    __syncthreads();
    return r;
}

__device__ __forceinline__ float blockReduceMax(float v, float* sh) {
    int lane = threadIdx.x & 31, w = threadIdx.x >> 5;
    #pragma unroll
    for (int o = 16; o; o >>= 1) v = fmaxf(v, __shfl_down_sync(0xffffffffu, v, o));
    if (lane == 0) sh[w] = v;
    __syncthreads();
    if (w == 0) {
        float r = (lane < (int)(blockDim.x >> 5)) ? sh[lane] : -1e30f;
        #pragma unroll
        for (int o = 16; o; o >>= 1) r = fmaxf(r, __shfl_down_sync(0xffffffffu, r, o));
        if (lane == 0) sh[0] = r;
    }
    __syncthreads();
    float r = sh[0];
    __syncthreads();
    return r;
}

// GroupNorm: one block per (batch, group); fp32 in, fp16 out.
__global__ __launch_bounds__(256) void gn_kernel(const float* __restrict__ x,
                                                 const float* __restrict__ scale,
                                                 const float* __restrict__ bias) {
    __shared__ float sh[32];
    int b = blockIdx.x >> 5;
    int g = blockIdx.x & 31;
    const int VE = 16 * NSP / 4;   // 4096 float4
    const long base = ((long)b * CCH + (long)g * 16) * NSP;
    const float4* xp = (const float4*)(x + base);
    float s = 0.f, ss = 0.f;
    for (int i = threadIdx.x; i < VE; i += 256) {
        float4 t = xp[i];
        s  += t.x + t.y + t.z + t.w;
        ss += t.x * t.x + t.y * t.y + t.z * t.z + t.w * t.w;
    }
    s  = blockReduceSum(s, sh);
    ss = blockReduceSum(ss, sh);
    float mean = s * (1.f / 16384.f);
    float var  = ss * (1.f / 16384.f) - mean * mean;
    float rinv = rsqrtf(var + 1e-5f);
    uint2* hp = (uint2*)(g_h + base);
    for (int i = threadIdx.x; i < VE; i += 256) {
        int c = g * 16 + (i >> 8);
        float sc = scale[c] * rinv;
        float bi = bias[c] - mean * sc;
        float4 t = xp[i];
        uint2 o;
        o.x = pkh(t.x * sc + bi, t.y * sc + bi);
        o.y = pkh(t.z * sc + bi, t.w * sc + bi);
        hp[i] = o;
    }
}

// Convert weights to fp16: wq | wk | wv | wo*WSCALE.  Pack q/k biases.
__global__ __launch_bounds__(256) void convw_kernel(const float* __restrict__ wq,
                                                    const float* __restrict__ wk,
                                                    const float* __restrict__ wv,
                                                    const float* __restrict__ wo,
                                                    const float* __restrict__ bq,
                                                    const float* __restrict__ bk) {
    const float* s = blockIdx.y == 0 ? wq : blockIdx.y == 1 ? wk : blockIdx.y == 2 ? wv : wo;
    float mul = (blockIdx.y == 3) ? WSCALE : 1.0f;
    f16* d = g_w16 + (long)blockIdx.y * CCH * CCH;
    int iv = blockIdx.x * 256 + threadIdx.x;      // float4 index, 65536 total
    float4 v = ((const float4*)s)[iv];
    uint2 o;
    o.x = pkh(v.x * mul, v.y * mul);
    o.y = pkh(v.z * mul, v.w * mul);
    ((uint2*)d)[iv] = o;
    if (blockIdx.y == 0 && blockIdx.x < 4) {
        int i = blockIdx.x * 256 + threadIdx.x;   // 0..1023
        g_bqk[i] = i < 512 ? bq[i] : bk[i - 512];
    }
}

// bvo[o] = dot(wo[o,:], bv) + bo[o].  One warp per output row.
__global__ __launch_bounds__(256) void bvo_kernel(const float* __restrict__ wo,
                                                  const float* __restrict__ bv,
                                                  const float* __restrict__ bo) {
    int o = blockIdx.x * 8 + (threadIdx.x >> 5);
    int lane = threadIdx.x & 31;
    const float* row = wo + (long)o * CCH;
    float s = 0.f;
    for (int c = lane; c < CCH; c += 32) s += row[c] * bv[c];
    #pragma unroll
    for (int off = 16; off; off >>= 1) s += __shfl_down_sync(0xffffffffu, s, off);
    if (lane == 0) g_bvo[o] = s + bo[o];
}

// Row softmax over 1024 fp16, in place, single pass (row in registers).
__global__ __launch_bounds__(256) void softmax_kernel(f16* __restrict__ attn) {
    __shared__ float sh[32];
    uint2* p = (uint2*)(attn + (long)blockIdx.x * NSP);
    uint2 raw = p[threadIdx.x];
    __half2 h0 = *(__half2*)&raw.x;
    __half2 h1 = *(__half2*)&raw.y;
    float a = __low2float(h0), b = __high2float(h0);
    float c = __low2float(h1), d = __high2float(h1);
    float m = fmaxf(fmaxf(a, b), fmaxf(c, d));
    m = blockReduceMax(m, sh);
    a = __expf(a - m); b = __expf(b - m); c = __expf(c - m); d = __expf(d - m);
    float s = a + b + c + d;
    s = blockReduceSum(s, sh);
    float inv = 1.f / s;
    raw.x = pkh(a * inv, b * inv);
    raw.y = pkh(c * inv, d * inv);
    p[threadIdx.x] = raw;
}

// Tensor-core batched GEMM, fp16 in / fp16 acc, cp.async double-buffered.
// C[b][i][j] = sum_k A[i*sAm + k*sAk] * B[k*sBk + j*sBn]   (+epilogue)
// AMODE 0: sAk==1 (k-fast)   AMODE 1: sAm==1 (m-fast)
// BMODE 0: sBn==1 (n-fast)   BMODE 1: sBk==1 (k-fast)
// EPI 0: direct fp16 fragment store
// EPI 1: fp16 out; v = acc*(row<scaleRows ? alpha : 1) + bias[row]
// EPI 2: fp32 out; v = acc*alpha + bias[row] + res[row*ldo+col]
// CTA tile 128x128, 4 warps in 2x2, warp tile 64x64, 4 CTAs/SM.
template<int AMODE, int BMODE, int EPI>
__global__ void __launch_bounds__(NTHR, 4) gemm_tc(
    const f16* __restrict__ A, const f16* __restrict__ B,
    const float* __restrict__ bias, const float* __restrict__ res,
    void* __restrict__ Cv, int Nn, int K,
    long sAm, long sAk, long sBk, long sBn,
    long batchA, long batchB, long batchC,
    float alpha, int scaleRows)
{
    constexpr int AS_STR = (AMODE == 0) ? BK + PAD : BM + PAD;
    constexpr int A_TILE = (AMODE == 0) ? BM * AS_STR : BK * AS_STR;
    constexpr int BS_STR = (BMODE == 0) ? BN + PAD : BK + PAD;
    constexpr int B_TILE = (BMODE == 0) ? BK * BS_STR : BN * BS_STR;
    using AL = typename Sel<AMODE == 0, wmma::row_major, wmma::col_major>::type;
    using BL = typename Sel<BMODE == 0, wmma::row_major, wmma::col_major>::type;

    extern __shared__ __align__(16) f16 sm[];
    f16* As = sm;
    f16* Bs = sm + 2 * A_TILE;

    const int bz = blockIdx.z;
    A += (long)bz * batchA;
    B += (long)bz * batchB;
    const int tid = threadIdx.x;
    const int warp = tid >> 5, lane = tid & 31;
    const int wn = warp & 1, wm = warp >> 1;     // warp tile 64(M) x 64(N)
    const int rowBase = blockIdx.y * BM;
    const int colBase = blockIdx.x * BN;

    wmma::fragment<wmma::accumulator, 16, 16, 16, f16> acc[4][4];
    #pragma unroll
    for (int i = 0; i < 4; i++)
        #pragma unroll
        for (int j = 0; j < 4; j++) wmma::fill_fragment(acc[i][j], __float2half(0.f));

    auto stage = [&](int kt, int buf) {
        int k0 = kt * BK;
        #pragma unroll
        for (int t = 0; t < 4; t++) {
            int ci = tid + t * NTHR;
            const f16* ga; f16* sa;
            if (AMODE == 0) {
                int m = ci >> 2, kv = (ci & 3) * 8;
                ga = A + (long)(rowBase + m) * sAm + (k0 + kv);
                sa = As + buf * A_TILE + m * AS_STR + kv;
            } else {
                int kk = ci >> 4, mv = (ci & 15) * 8;
                ga = A + (rowBase + mv) + (long)(k0 + kk) * sAk;
                sa = As + buf * A_TILE + kk * AS_STR + mv;
            }
            cp16(sa, ga);
        }
        #pragma unroll
        for (int t = 0; t < 4; t++) {
            int ci = tid + t * NTHR;
            const f16* gb; f16* sb;
            if (BMODE == 0) {
                int kk = ci >> 4, nv = (ci & 15) * 8;
                gb = B + (long)(k0 + kk) * sBk + (colBase + nv);
                sb = Bs + buf * B_TILE + kk * BS_STR + nv;
            } else {
                int n = ci >> 2, kv = (ci & 3) * 8;
                gb = B + (long)(colBase + n) * sBn + (k0 + kv);
                sb = Bs + buf * B_TILE + n * BS_STR + kv;
            }
            cp16(sb, gb);
        }
        cp_commit();
    };

    const int KT = K >> 5;
    stage(0, 0);
    for (int kt = 0; kt < KT; kt++) {
        int buf = kt & 1;
        if (kt + 1 < KT) { stage(kt + 1, buf ^ 1); cp_wait1(); }
        else cp_wait0();
        __syncthreads();
        #pragma unroll
        for (int ks = 0; ks < BK; ks += 16) {
            wmma::fragment<wmma::matrix_a, 16, 16, 16, f16, AL> af[4];
            #pragma unroll
            for (int i = 0; i < 4; i++) {
                const f16* ap = (AMODE == 0)
                    ? As + buf * A_TILE + (wm * 64 + i * 16) * AS_STR + ks
                    : As + buf * A_TILE + ks * AS_STR + (wm * 64 + i * 16);
                wmma::load_matrix_sync(af[i], ap, AS_STR);
            }
            #pragma unroll
            for (int j = 0; j < 4; j++) {
                wmma::fragment<wmma::matrix_b, 16, 16, 16, f16, BL> bfm;
                const f16* bp = (BMODE == 0)
                    ? Bs + buf * B_TILE + ks * BS_STR + (wn * 64 + j * 16)
                    : Bs + buf * B_TILE + (wn * 64 + j * 16) * BS_STR + ks;
                wmma::load_matrix_sync(bfm, bp, BS_STR);
                #pragma unroll
                for (int i = 0; i < 4; i++)
                    wmma::mma_sync(acc[i][j], af[i], bfm, acc[i][j]);
            }
        }
        __syncthreads();
    }

    const long cbatch = (long)bz * batchC;

    if (EPI == 0) {
        // Direct fp16 fragment stores to global.
        f16* Cb = (f16*)Cv + cbatch;
        #pragma unroll
        for (int i = 0; i < 4; i++) {
            #pragma unroll
            for (int j = 0; j < 4; j++) {
                f16* cp = Cb + (long)(rowBase + wm * 64 + i * 16) * Nn
                             + colBase + wn * 64 + j * 16;
                wmma::store_matrix_sync(cp, acc[i][j], Nn, wmma::mem_row_major);
            }
        }
        return;
    }

    // Bounce epilogue: fp16 frag -> smem -> processed stores.
    f16* cw = sm + warp * (16 * 24);
    const int r  = lane >> 1;
    const int cb = (lane & 1) * 8;
    #pragma unroll
    for (int i = 0; i < 4; i++) {
        #pragma unroll
        for (int j = 0; j < 4; j++) {
            wmma::store_matrix_sync(cw, acc[i][j], 24, wmma::mem_row_major);
            __syncwarp();
            uint2 raw = *(uint2*)(cw + r * 24 + cb);
            __syncwarp();
            __half2 p0 = *(__half2*)&raw.x;
            __half2 p1 = *(__half2*)&raw.y;
            float f0 = __low2float(p0), f1 = __high2float(p0);
            float f2 = __low2float(p1), f3 = __high2float(p1);
            uint2 raw2 = *(uint2*)(cw + r * 24 + cb + 4);
            __half2 p2 = *(__half2*)&raw2.x;
            __half2 p3 = *(__half2*)&raw2.y;
            float f4 = __low2float(p2), f5 = __high2float(p2);
            float f6 = __low2float(p3), f7 = __high2float(p3);
            int row = rowBase + wm * 64 + i * 16 + r;
            long coff = cbatch + (long)row * Nn + colBase + wn * 64 + j * 16 + cb;
            float ba = bias[row];
            if (EPI == 1) {
                float a = (row < scaleRows) ? alpha : 1.f;
                f0 = f0 * a + ba; f1 = f1 * a + ba; f2 = f2 * a + ba; f3 = f3 * a + ba;
                f4 = f4 * a + ba; f5 = f5 * a + ba; f6 = f6 * a + ba; f7 = f7 * a + ba;
                uint4 u;
                u.x = pkh(f0, f1); u.y = pkh(f2, f3);
                u.z = pkh(f4, f5); u.w = pkh(f6, f7);
                *(uint4*)((f16*)Cv + coff) = u;
            } else {
                const float4* rp = (const float4*)(res + coff);
                float4 r0 = rp[0], r1 = rp[1];
                float4 v0, v1;
                v0.x = f0 * alpha + ba + r0.x; v0.y = f1 * alpha + ba + r0.y;
                v0.z = f2 * alpha + ba + r0.z; v0.w = f3 * alpha + ba + r0.w;
                v1.x = f4 * alpha + ba + r1.x; v1.y = f5 * alpha + ba + r1.y;
                v1.z = f6 * alpha + ba + r1.z; v1.w = f7 * alpha + ba + r1.w;
                float* Cf = (float*)Cv;
                *(float4*)(Cf + coff) = v0;
                *(float4*)(Cf + coff + 4) = v1;
            }
        }
    }
}

#define GSM (42 * 1024)

extern "C" void kernel_launch(void* const* d_in, const int* in_sizes, int n_in,
                              void* d_out, int out_size) {
    const float* x  = (const float*)d_in[0];
    const float* gs = (const float*)d_in[1];
    const float* gb = (const float*)d_in[2];
    const float* wq = (const float*)d_in[3];
    const float* bq = (const float*)d_in[4];
    const float* wk = (const float*)d_in[5];
    const float* bk = (const float*)d_in[6];
    const float* wv = (const float*)d_in[7];
    const float* bv = (const float*)d_in[8];
    const float* wo = (const float*)d_in[9];
    const float* bo = (const float*)d_in[10];
    float* out = (float*)d_out;

    f16 *h, *qk, *attn, *vo, *w16, *wvo;
    float *bqk, *bvo;
    cudaGetSymbolAddress((void**)&h,    g_h);
    cudaGetSymbolAddress((void**)&qk,   g_qk);
    cudaGetSymbolAddress((void**)&attn, g_attn);
    cudaGetSymbolAddress((void**)&vo,   g_vo);
    cudaGetSymbolAddress((void**)&w16,  g_w16);
    cudaGetSymbolAddress((void**)&wvo,  g_wvo);
    cudaGetSymbolAddress((void**)&bqk,  g_bqk);
    cudaGetSymbolAddress((void**)&bvo,  g_bvo);

    const long CN  = (long)CCH * NSP;   // 524288
    const long NN  = (long)NSP * NSP;   // 1048576
    const long WW  = (long)CCH * CCH;   // 262144
    const float scl = 1.0f / sqrtf((float)CCH);
    const float inv_ws = 1.0f / WSCALE;

    cudaFuncSetAttribute(gemm_tc<0,0,0>, cudaFuncAttributeMaxDynamicSharedMemorySize, GSM);
    cudaFuncSetAttribute(gemm_tc<0,0,1>, cudaFuncAttributeMaxDynamicSharedMemorySize, GSM);
    cudaFuncSetAttribute(gemm_tc<1,0,0>, cudaFuncAttributeMaxDynamicSharedMemorySize, GSM);
    cudaFuncSetAttribute(gemm_tc<0,1,2>, cudaFuncAttributeMaxDynamicSharedMemorySize, GSM);

    // 1) GroupNorm -> h (fp16); weights -> fp16 (wo pre-scaled); bvo vector
    gn_kernel<<<BSZ * NGROUPS, 256>>>(x, gs, gb);
    convw_kernel<<<dim3(WW / 4 / 256, 4), 256>>>(wq, wk, wv, wo, bq, bk);
    bvo_kernel<<<CCH / 8, 256>>>(wo, bv, bo);

    // 2) wvo = (wo*WSCALE) @ wv  [512,512], K=512, single batch
    gemm_tc<0,0,0><<<dim3(CCH / BN, CCH / BM, 1), NTHR, GSM>>>(
        w16 + 3*WW, w16 + 2*WW, nullptr, nullptr, wvo,
        CCH, CCH, CCH, 1, CCH, 1, 0, 0, 0, 1.f, 0);

    // 3) Fused QK projection: [1024,512] @ [512,1024] per batch.
    //    q rows (0..511) get *scl folded in; bias added for all rows.
    dim3 gQK(NSP / BN, 2 * CCH / BM, BSZ);
    gemm_tc<0,0,1><<<gQK, NTHR, GSM>>>(w16, h, bqk, nullptr, qk,
        NSP, CCH, CCH, 1, NSP, 1, 0, CN, NN, scl, CCH);

    // 4) vo = wvo @ h  (M=512, N=1024, K=512) per batch
    dim3 gVO(NSP / BN, CCH / BM, BSZ);
    gemm_tc<0,0,0><<<gVO, NTHR, GSM>>>(wvo, h, nullptr, nullptr, vo,
        NSP, CCH, CCH, 1, NSP, 1, 0, CN, CN, 1.f, 0);

    // 5) Scores: S[n,m] = sum_c q[c,n] k[c,m]  (scl pre-folded into q)
    dim3 gScore(NSP / BN, NSP / BM, BSZ);
    gemm_tc<1,0,0><<<gScore, NTHR, GSM>>>(
        qk, qk + CN, nullptr, nullptr, attn,
        NSP, CCH, 1, NSP, NSP, 1, NN, NN, NN, 1.f, 0);

    // 6) Row softmax (fp16 in/out)
    softmax_kernel<<<BSZ * NSP, 256>>>(attn);

    // 7) out[o,n] = (1/WSCALE) * sum_m vo[o,m] attn[n,m] + bvo[o] + x  (fp32)
    dim3 gFin(NSP / BN, CCH / BM, BSZ);
    gemm_tc<0,1,2><<<gFin, NTHR, GSM>>>(
        vo, attn, bvo, x, out,
        NSP, NSP, NSP, 1, 1, NSP, CN, NN, CN, inv_ws, 0);
}